// round 2
// baseline (speedup 1.0000x reference)
#include <cuda_runtime.h>

// BottomUp_57131654972209: adding-doubling radiative transfer.
// Shapes: a,r,t,s : (E, L=60, C=48) fp32. Outputs flux_up, flux_down, absorbed : (E, 59, 48).
// One thread per (e,c) column. Fused reverse scan (surface reflection + upward flux,
// using d[l] == 1 - tmp[l]) then forward scan (downward flux + absorbed).
// Divisions replaced by a bounded series for 1/(1 - tmp^2) (tmp <= 0.209 provably).

#define LAY 60
#define NC  48
#define LM1 59

__global__ void __launch_bounds__(256, 1)
adding_doubling_kernel(const float* __restrict__ A,
                       const float* __restrict__ R,
                       const float* __restrict__ T,
                       const float* __restrict__ S,
                       float* __restrict__ Fup,
                       float* __restrict__ Fdn,
                       float* __restrict__ Abs,
                       int ncol)
{
    int tid = blockIdx.x * blockDim.x + threadIdx.x;
    if (tid >= ncol) return;

    const int e = tid / NC;
    const int c = tid - e * NC;
    const int ibase = e * (LAY * NC) + c;   // input column base
    const int obase = e * (LM1 * NC) + c;   // output column base

    // Per-layer coefficients carried from reverse pass to forward pass.
    float ssum[LM1];  // s_multi_down + s_multi_up_down
    float tmul[LM1];  // t_multi
    float amul[LM1];  // a_multi
    float aup [LM1];  // absorbed_up = a * flux_up

    // --- init step (l = 59): rs_body[59] from carry = r[59] ---
    const float r59 = R[ibase + 59 * NC];
    const float t59 = T[ibase + 59 * NC];
    // exact division here is once per thread (negligible MUFU)
    float rs = (r59 + r59 * t59 * t59) / (1.0f - r59 * r59);

    float fup_carry = 0.0f;
    float s_next = S[ibase + 59 * NC];   // s[l+1] for l = 58

    // --- reverse pass: l = 58 .. 0 ---
    #pragma unroll
    for (int l = LM1 - 1; l >= 0; --l) {
        const float rl  = R[ibase + l * NC];
        const float tl  = T[ibase + l * NC];
        const float sl  = S[ibase + l * NC];
        const float al  = A[ibase + l * NC];
        const float sl1 = s_next;
        s_next = sl;

        // rs currently holds rs_body[l+1] == rs_below[l]
        const float tmp = rs * rl;                 // <= ~0.209
        const float u   = tmp * tmp;               // <= ~0.0437
        // invu = 1/(1-u) = 1 + u + u^2 + u^3 + u^4  (rel err ~ u^5 < 2e-7)
        const float invu  = fmaf(u, fmaf(u, fmaf(u, fmaf(u, 1.0f, 1.0f), 1.0f), 1.0f), 1.0f);
        const float inv1p = (1.0f - tmp) * invu;   // 1/(1+tmp)
        const float inv1m = (1.0f + tmp) * invu;   // 1/(1-tmp) == 1/d[l]

        // upward flux (reverse scan), d[l] = 1 - tmp
        const float su  = sl1 * fmaf(tmp, inv1p, 1.0f);      // s_multi_up
        const float sd  = sl * rs * inv1p;                    // s_multi_down_up
        const float fup = fup_carry + su + sd;
        Fup[obase + l * NC] = fup;
        aup[l] = al * fup;                                    // absorbed_up
        fup_carry = fup * tl * inv1m;                         // * t / d

        // forward-pass coefficients
        tmul[l] = tl * inv1p;                                 // t_multi = t/(1+tmp)
        amul[l] = al * fmaf(tl * rs, inv1p, 1.0f);            // a_multi
        ssum[l] = sl * fmaf(tmp, inv1m, 1.0f)                 // s_multi_down
                + sl1 * rl * inv1m;                           // + s_multi_up_down

        // surface reflection recurrence: rs_body[l] = (r + rs*t^2) / (1 - tmp)
        rs = fmaf(rs, tl * tl, rl) * inv1m;
    }

    // --- forward pass: l = 0 .. 58 (downward flux + absorbed) ---
    float fd = 0.0f;
    #pragma unroll
    for (int l = 0; l < LM1; ++l) {
        fd += ssum[l];
        Fdn[obase + l * NC] = fd;
        Abs[obase + l * NC] = fmaf(amul[l], fd, aup[l]);
        fd *= tmul[l];
    }
}

extern "C" void kernel_launch(void* const* d_in, const int* in_sizes, int n_in,
                              void* d_out, int out_size)
{
    const float* A = (const float*)d_in[0];
    const float* R = (const float*)d_in[1];
    const float* T = (const float*)d_in[2];
    const float* S = (const float*)d_in[3];

    const int total = in_sizes[0];       // E * L * C
    const int ncol  = total / LAY;       // E * C
    const int nper  = ncol * LM1;        // elements per output tensor

    float* out  = (float*)d_out;
    float* fup  = out;
    float* fdn  = out + nper;
    float* absd = out + 2 * nper;

    const int block = 256;
    const int grid  = (ncol + block - 1) / block;
    adding_doubling_kernel<<<grid, block>>>(A, R, T, S, fup, fdn, absd, ncol);
}

// round 3
// speedup vs baseline: 1.0108x; 1.0108x over previous
#include <cuda_runtime.h>

// BottomUp_57131654972209: adding-doubling radiative transfer.
// Shapes: a,r,t,s : (E, L=60, C=48) fp32. Outputs flux_up, flux_down, absorbed : (E, 59, 48).
// One thread per (e,c) column. Fused reverse scan (surface reflection + upward flux,
// using d[l] == 1 - tmp[l]) then forward scan (downward flux + absorbed).
// Divisions replaced by a bounded series for 1/(1 - tmp^2) (tmp <= 0.209 provably).

#define LAY 60
#define NC  48
#define LM1 59

__global__ void __launch_bounds__(256, 1)
adding_doubling_kernel(const float* __restrict__ A,
                       const float* __restrict__ R,
                       const float* __restrict__ T,
                       const float* __restrict__ S,
                       float* __restrict__ Fup,
                       float* __restrict__ Fdn,
                       float* __restrict__ Abs,
                       int ncol)
{
    int tid = blockIdx.x * blockDim.x + threadIdx.x;
    if (tid >= ncol) return;

    const int e = tid / NC;
    const int c = tid - e * NC;
    const int ibase = e * (LAY * NC) + c;   // input column base
    const int obase = e * (LM1 * NC) + c;   // output column base

    // Per-layer coefficients carried from reverse pass to forward pass.
    float ssum[LM1];  // s_multi_down + s_multi_up_down
    float tmul[LM1];  // t_multi
    float amul[LM1];  // a_multi
    float aup [LM1];  // absorbed_up = a * flux_up

    // --- init step (l = 59): rs_body[59] from carry = r[59] ---
    const float r59 = R[ibase + 59 * NC];
    const float t59 = T[ibase + 59 * NC];
    // exact division here is once per thread (negligible MUFU)
    float rs = (r59 + r59 * t59 * t59) / (1.0f - r59 * r59);

    float fup_carry = 0.0f;
    float s_next = S[ibase + 59 * NC];   // s[l+1] for l = 58

    // --- reverse pass: l = 58 .. 0 ---
    #pragma unroll
    for (int l = LM1 - 1; l >= 0; --l) {
        const float rl  = R[ibase + l * NC];
        const float tl  = T[ibase + l * NC];
        const float sl  = S[ibase + l * NC];
        const float al  = A[ibase + l * NC];
        const float sl1 = s_next;
        s_next = sl;

        // rs currently holds rs_body[l+1] == rs_below[l]
        const float tmp = rs * rl;                 // <= ~0.209
        const float u   = tmp * tmp;               // <= ~0.0437
        // invu = 1/(1-u) = 1 + u + u^2 + u^3 + u^4  (rel err ~ u^5 < 2e-7)
        const float invu  = fmaf(u, fmaf(u, fmaf(u, fmaf(u, 1.0f, 1.0f), 1.0f), 1.0f), 1.0f);
        const float inv1p = (1.0f - tmp) * invu;   // 1/(1+tmp)
        const float inv1m = (1.0f + tmp) * invu;   // 1/(1-tmp) == 1/d[l]

        // upward flux (reverse scan), d[l] = 1 - tmp
        const float su  = sl1 * fmaf(tmp, inv1p, 1.0f);      // s_multi_up
        const float sd  = sl * rs * inv1p;                    // s_multi_down_up
        const float fup = fup_carry + su + sd;
        Fup[obase + l * NC] = fup;
        aup[l] = al * fup;                                    // absorbed_up
        fup_carry = fup * tl * inv1m;                         // * t / d

        // forward-pass coefficients
        tmul[l] = tl * inv1p;                                 // t_multi = t/(1+tmp)
        amul[l] = al * fmaf(tl * rs, inv1p, 1.0f);            // a_multi
        ssum[l] = sl * fmaf(tmp, inv1m, 1.0f)                 // s_multi_down
                + sl1 * rl * inv1m;                           // + s_multi_up_down

        // surface reflection recurrence: rs_body[l] = (r + rs*t^2) / (1 - tmp)
        rs = fmaf(rs, tl * tl, rl) * inv1m;
    }

    // --- forward pass: l = 0 .. 58 (downward flux + absorbed) ---
    float fd = 0.0f;
    #pragma unroll
    for (int l = 0; l < LM1; ++l) {
        fd += ssum[l];
        Fdn[obase + l * NC] = fd;
        Abs[obase + l * NC] = fmaf(amul[l], fd, aup[l]);
        fd *= tmul[l];
    }
}

extern "C" void kernel_launch(void* const* d_in, const int* in_sizes, int n_in,
                              void* d_out, int out_size)
{
    const float* A = (const float*)d_in[0];
    const float* R = (const float*)d_in[1];
    const float* T = (const float*)d_in[2];
    const float* S = (const float*)d_in[3];

    const int total = in_sizes[0];       // E * L * C
    const int ncol  = total / LAY;       // E * C
    const int nper  = ncol * LM1;        // elements per output tensor

    float* out  = (float*)d_out;
    float* fup  = out;
    float* fdn  = out + nper;
    float* absd = out + 2 * nper;

    const int block = 256;
    const int grid  = (ncol + block - 1) / block;
    adding_doubling_kernel<<<grid, block>>>(A, R, T, S, fup, fdn, absd, ncol);
}